// round 11
// baseline (speedup 1.0000x reference)
#include <cuda_runtime.h>
#include <cuda_fp16.h>
#include <cstdint>
#include <cstddef>

// Problem constants
#define TT 20
#define BB 1024
#define DD 2312
#define D4 578            // DD / 4, exact

// Persistent kernel: 147 blocks x 896 threads, 1 block/SM (~139KB smem).
// Blocks 0..145 own 7 rows each; block 146 owns rows 1022..1023.
#define NBLK 147
#define NTHR 896
#define GSZ  128          // threads per row-group
#define NGRP 7            // max rows per block
#define NS4  5            // ceil(578/128) float4 slots per thread
#define TAIL4 66          // 578 - 4*128

#define L2E 1.4426950408889634f

// Value-carrying grid barrier: per-step slots. g_rel[k] holds the released
// binding strength (float bits | 0x80000000 flag; bs >= 0 so sign bit free).
// Slot k is cleaned by the releaser of barrier k+2 (all blocks provably past
// their consume of slot k by then); slots TT-2 and TT-1 are cleaned by every
// block at launch start (before its arrive(0), which happens-before any block
// can reach barrier TT-2 accumulation) -> graph replays are deterministic.
__device__ unsigned g_cnt[TT];
__device__ float    g_bsum[TT];
__device__ unsigned g_rel[TT];

__device__ __forceinline__ float warp_sum(float v) {
#pragma unroll
    for (int o = 16; o > 0; o >>= 1)
        v += __shfl_xor_sync(0xffffffffu, v, o);
    return v;
}

__device__ __forceinline__ float ex2a(float x) {
    float y; asm("ex2.approx.ftz.f32 %0, %1;" : "=f"(y) : "f"(x)); return y;
}
__device__ __forceinline__ float rcpa(float x) {
    float y; asm("rcp.approx.ftz.f32 %0, %1;" : "=f"(y) : "f"(x)); return y;
}
__device__ __forceinline__ float tanha(float x) {
    float y; asm("tanh.approx.f32 %0, %1;" : "=f"(y) : "f"(x)); return y;
}
// exact-path sigmoid (2 MUFU) — used only in one-time init
__device__ __forceinline__ float sigm(float x) {
    return rcpa(1.0f + ex2a(-x * L2E));
}
// 1-MUFU sigmoid via tanh (measured abs err ~1e-5; safe on all paths here)
__device__ __forceinline__ float sigm_t(float x) {
    return fmaf(0.5f, tanha(0.5f * x), 0.5f);
}

__device__ __forceinline__ void cpasync16(uint32_t saddr, const void* g) {
    asm volatile("cp.async.cg.shared.global [%0], [%1], 16;" :: "r"(saddr), "l"(g));
}
#define CP_COMMIT() asm volatile("cp.async.commit_group;" ::: "memory")
#define CP_WAIT0()  asm volatile("cp.async.wait_group 0;" ::: "memory")

__global__ void __launch_bounds__(NTHR, 1)
snn_etad_kernel(const float* __restrict__ x,
                const float* __restrict__ ac,
                const float* __restrict__ tw,
                const float* __restrict__ ig,
                const float* __restrict__ p_md,
                const float* __restrict__ p_sd,
                const float* __restrict__ p_th,
                float* __restrict__ out)
{
    extern __shared__ char smraw[];
    float4*  s_xb = (float4*)smraw;                     // NGRP*D4 (x stage)
    __half2* s_c  = (__half2*)(s_xb + NGRP * D4);       // 2*NGRP*D4*2 half2
    __half2* s_ag = s_c + 2 * NGRP * D4 * 2;            // DD half2 {a, g}
    float*   s_rS = (float*)(s_ag + DD);                // 32
    float*   s_rW = s_rS + 32;                          // 32
    float*   s_rA = s_rW + 32;                          // 2 x 32 ping-pong
    float*   s_bsv = s_rA + 64;                         // 1
    volatile int* s_step = (volatile int*)(s_bsv + 1);  // 1

    const int tid  = threadIdx.x;
    const int grp  = tid >> 7;         // 0..6 row-group
    const int gtid = tid & 127;
    const int w    = tid >> 5;         // 0..27
    const int lane = tid & 31;

    int nrows = BB - NGRP * (int)blockIdx.x;
    nrows = nrows > NGRP ? NGRP : nrows;          // 7 or 2 (block 146)
    const bool rowact = grp < nrows;
    const int b = NGRP * blockIdx.x + grp;        // valid when rowact

    const float md = p_md[0];
    const float sd = p_sd[0];
    const float th = p_th[0];
    const float hth = 0.5f * th;
    const float inv_bd = 1.0f / (float)(BB * DD);

    const uint32_t xb_u32 =
        (uint32_t)__cvta_generic_to_shared(s_xb) + (uint32_t)(grp * D4) * 16u;
    const float4* s_xbr = s_xb + grp * D4;

    // Init per-feature gates (fp16 packed {a, g})
    for (int idx = tid; idx < DD; idx += NTHR) {
        const float a = ac[idx];
        const float g = sigm(tw[idx]) * sigm(ig[idx]);
        s_ag[idx] = __floats2half2_rn(a, g);
    }
    if (tid == 0) {
        *s_step = 0;
        // clean the two slots the previous launch left dirty (safe: every
        // block does this before its arrive(0); nothing touches these slots
        // until all blocks passed barrier TT-3)
        atomicExch(&g_cnt[TT - 2], 0u);  atomicExch(&g_cnt[TT - 1], 0u);
        atomicExch(&g_bsum[TT - 2], 0.f); atomicExch(&g_bsum[TT - 1], 0.f);
        atomicExch(&g_rel[TT - 2], 0u);  atomicExch(&g_rel[TT - 1], 0u);
    }
    __syncthreads();

    // LIF state in registers (thread-private across all steps)
    float4 ir[NS4], vr[NS4];
#pragma unroll
    for (int s = 0; s < NS4; ++s) {
        ir[s] = make_float4(0.f, 0.f, 0.f, 0.f);
        vr[s] = make_float4(0.f, 0.f, 0.f, 0.f);
    }

    // issue cp.async of x(t) into the smem stage (thread-private slots)
    auto issue_x = [&](int t) {
        if (!rowact || t >= TT) return;
        const float4* xrow4 = (const float4*)(x + ((size_t)t * BB + b) * DD);
#pragma unroll
        for (int s = 0; s < NS4; ++s) {
            const int d4 = s * GSZ + gtid;
            const bool act = (s < NS4 - 1) || (gtid < TAIL4);
            if (act) cpasync16(xb_u32 + (uint32_t)d4 * 16u, xrow4 + d4);
        }
        CP_COMMIT();
    };

    // ============ pass1+pass2 for timestep t (x(t) already staged in smem):
    // writes c(t) fp16 into ping-pong slot (t&1), issues cp.async for x(t+1),
    // returns this warp's |c| sum (0 for inactive groups).
    auto compute_c = [&](int t) -> float {
        if (!rowact) return 0.0f;
        CP_WAIT0();   // x(t) stage complete (issued >= one pass3 ago)

        float S = 0.0f, W = 0.0f;
#pragma unroll
        for (int s = 0; s < NS4; ++s) {
            const int d4 = s * GSZ + gtid;
            const bool act = (s < NS4 - 1) || (gtid < TAIL4);
            if (act) {
                const float4 v = s_xbr[d4];
                float e;
                e = ex2a(v.x * L2E); S += e; W += v.x * e;
                e = ex2a(v.y * L2E); S += e; W += v.y * e;
                e = ex2a(v.z * L2E); S += e; W += v.z * e;
                e = ex2a(v.w * L2E); S += e; W += v.w * e;
            }
        }
        S = warp_sum(S);
        W = warp_sum(W);
        if (lane == 0) { s_rS[w] = S; s_rW[w] = W; }
        asm volatile("bar.sync %0, %1;" :: "r"(grp + 1), "n"(GSZ) : "memory");
        S = s_rS[grp * 4 + 0] + s_rS[grp * 4 + 1] + s_rS[grp * 4 + 2] + s_rS[grp * 4 + 3];
        W = s_rW[grp * 4 + 0] + s_rW[grp * 4 + 1] + s_rW[grp * 4 + 2] + s_rW[grp * 4 + 3];
        // entropy = lnS - W/S - D*1e-8  (shift-invariant; |x|<~6 so no overflow)
        const float ent = __logf(S) - __fdividef(W, S) - (float)DD * 1e-8f;

        __half2* sc2 = s_c + ((unsigned)t & 1) * (NGRP * D4 * 2) + grp * (D4 * 2);
        float asum = 0.0f;
#pragma unroll
        for (int s = 0; s < NS4; ++s) {
            const int d4 = s * GSZ + gtid;
            const bool act = (s < NS4 - 1) || (gtid < TAIL4);
            if (act) {
                const float4 v = s_xbr[d4];         // re-read (regs freed)
                const uint4 agp = *(const uint4*)(s_ag + 4 * d4);
                const float2 ag0 = __half22float2(((const __half2*)&agp)[0]);
                const float2 ag1 = __half22float2(((const __half2*)&agp)[1]);
                const float2 ag2 = __half22float2(((const __half2*)&agp)[2]);
                const float2 ag3 = __half22float2(((const __half2*)&agp)[3]);
                float4 c;
                c.x = v.x * sigm_t(ag0.x * ent) * ag0.y;
                c.y = v.y * sigm_t(ag1.x * ent) * ag1.y;
                c.z = v.z * sigm_t(ag2.x * ent) * ag2.y;
                c.w = v.w * sigm_t(ag3.x * ent) * ag3.y;
                sc2[d4 * 2 + 0] = __floats2half2_rn(c.x, c.y);
                sc2[d4 * 2 + 1] = __floats2half2_rn(c.z, c.w);
                asum += fabsf(c.x) + fabsf(c.y) + fabsf(c.z) + fabsf(c.w);
            }
        }
        // all my XB reads are done -> refill my slots with x(t+1)
        issue_x(t + 1);
        return warp_sum(asum);
    };

    // ============ block-level |c| sum -> s_rA ping-pong + sync + warp0 reduce
    auto post_asum = [&](int k, float asum) -> float {
        if (lane == 0) s_rA[((unsigned)k & 1) * 32 + w] = asum;
        __syncthreads();
        float tot = 0.0f;
        if (w == 0) {
            const float vv = (lane < (NTHR / 32)) ? s_rA[((unsigned)k & 1) * 32 + lane] : 0.0f;
            tot = warp_sum(vv);
        }
        return tot;  // valid in warp 0 only
    };

    // ============ tid0: arrive at barrier k; last arriver publishes the value
    auto arrive = [&](int k, float tot) {
        atomicAdd(&g_bsum[k], tot);
        __threadfence();
        const unsigned pos = atomicAdd(&g_cnt[k], 1);
        if (pos == NBLK - 1) {
            const float val = atomicAdd(&g_bsum[k], 0.0f);  // all adds visible
            if (k >= 2) {  // clean slot k-2 (quiescent: see header comment)
                atomicExch(&g_cnt[k - 2], 0u);
                atomicExch(&g_bsum[k - 2], 0.0f);
                atomicExch(&g_rel[k - 2], 0u);
            }
            __threadfence();
            atomicExch(&g_rel[k], __float_as_uint(val * inv_bd) | 0x80000000u);
        }
    };

    // ---------------- prologue: stage x(0); c(0) -> slot 0; arrive(0)
    {
        issue_x(0);
        float asum = compute_c(0);          // waits x(0), issues x(1)
        float tot = post_asum(0, asum);
        if (tid == 0) arrive(0, tot);
    }

    for (int t = 0; t < TT; ++t) {
        // ---- pass1+2 for t+1 (independent of bs(t)) hides barrier latency
        float tot = 0.0f;
        const bool has_next = (t + 1) < TT;
        if (has_next) {
            float asum = compute_c(t + 1);
            tot = post_asum(t + 1, asum);
        } else {
            __syncthreads();
        }

        // ---- tid0: arrive(t+1) first (releases others sooner), then consume
        //      the value-carrying release of barrier t and publish to smem
        if (tid == 0) {
            if (has_next) arrive(t + 1, tot);
            unsigned u;
            while ((u = *(volatile unsigned*)&g_rel[t]) == 0u) __nanosleep(32);
            *(volatile float*)s_bsv = __uint_as_float(u & 0x7fffffffu);
            __threadfence_block();
            *s_step = t + 1;                                  // publish
        }

        // ---- per-warp pickup (warps stagger straight into pass3)
        float bs;
        if (lane == 0) {
            while (*s_step < t + 1) { }
            bs = *(volatile float*)s_bsv;
        }
        bs = __shfl_sync(0xffffffffu, bs, 0);

        // ---- pass3: LIF on c(t) (fp16 ping-pong slot t&1), state in regs.
        if (rowact) {
            const __half2* sc2 = s_c + ((unsigned)t & 1) * (NGRP * D4 * 2) + grp * (D4 * 2);
            float4* o4 = (float4*)(out + ((size_t)t * BB + b) * DD);
#pragma unroll
            for (int s = 0; s < NS4; ++s) {
                const int d4 = s * GSZ + gtid;
                const bool act = (s < NS4 - 1) || (gtid < TAIL4);
                if (act) {
                    const float2 c01 = __half22float2(sc2[d4 * 2 + 0]);
                    const float2 c23 = __half22float2(sc2[d4 * 2 + 1]);
                    float4 sp;

                    ir[s].x = sd * ir[s].x + c01.x * bs;
                    vr[s].x = md * vr[s].x + ir[s].x;
                    sp.x = fmaf(0.5f, tanha(fmaf(0.5f, vr[s].x, -hth)), 0.5f);
                    vr[s].x -= sp.x * th;

                    ir[s].y = sd * ir[s].y + c01.y * bs;
                    vr[s].y = md * vr[s].y + ir[s].y;
                    sp.y = fmaf(0.5f, tanha(fmaf(0.5f, vr[s].y, -hth)), 0.5f);
                    vr[s].y -= sp.y * th;

                    ir[s].z = sd * ir[s].z + c23.x * bs;
                    vr[s].z = md * vr[s].z + ir[s].z;
                    sp.z = fmaf(0.5f, tanha(fmaf(0.5f, vr[s].z, -hth)), 0.5f);
                    vr[s].z -= sp.z * th;

                    ir[s].w = sd * ir[s].w + c23.y * bs;
                    vr[s].w = md * vr[s].w + ir[s].w;
                    sp.w = fmaf(0.5f, tanha(fmaf(0.5f, vr[s].w, -hth)), 0.5f);
                    vr[s].w -= sp.w * th;

                    __stcs(o4 + d4, sp);
                }
            }
        }
        // smem/global reuse safety across steps:
        // - XB slots are thread-private; refill issued only after the same
        //   thread's last LDS of the old contents (program order), and waited
        //   before the next read.
        // - c ping-pong: pass2(t+1) writes slot (t+1)&1, pass3(t) reads slot
        //   t&1; slot reuse at t+2 is by the same thread that read it at t.
        // - s_rS/s_rW rewritten at k+1 only after this warp's s_step poll for
        //   step k passed; step-k readers finished before post_asum(k)'s sync.
        // - s_rA ping-ponged. s_bsv/s_step monotonic within a launch.
        // - g_* slots are per-step; cleaned per the scheme in the header.
    }
}

extern "C" void kernel_launch(void* const* d_in, const int* in_sizes, int n_in,
                              void* d_out, int out_size)
{
    (void)in_sizes; (void)n_in; (void)out_size;
    const float* x  = (const float*)d_in[0];
    const float* ac = (const float*)d_in[1];
    const float* tw = (const float*)d_in[2];
    const float* ig = (const float*)d_in[3];
    const float* md = (const float*)d_in[4];
    const float* sd = (const float*)d_in[5];
    const float* th = (const float*)d_in[6];
    float* out = (float*)d_out;

    // bytes: XB 7*578*16 = 64736
    //      + c ping-pong 2*7*1156 half2 * 4B = 64736
    //      + ag DD half2 * 4B = 9248
    //      + rS(32)+rW(32)+rA(64)+bsv(1)+step(1) floats = 520
    constexpr size_t SMEM_BYTES =
        (size_t)(NGRP * D4) * 16 + (size_t)(2 * NGRP * D4 * 2) * 4
        + (size_t)DD * 4 + 130 * 4;   // 139,240 B

    cudaFuncSetAttribute(snn_etad_kernel,
                         cudaFuncAttributeMaxDynamicSharedMemorySize,
                         (int)SMEM_BYTES);

    snn_etad_kernel<<<NBLK, NTHR, SMEM_BYTES>>>(x, ac, tw, ig, md, sd, th, out);
}